// round 11
// baseline (speedup 1.0000x reference)
#include <cuda_runtime.h>
#include <cuda_fp16.h>
#include <cstdint>

// Problem constants
#define B_      4
#define C_IN_   32
#define C_OUT_  64
#define E_      200000
#define KK_     5
#define CKDIM   160
#define TILE_M  64
#define NTHR    512
#define NCH     20             // 16B chunks per row (160 fp16 k-values)

#define TILES_PER_B  3125      // 200000 / 64 exactly
#define TOTAL_TILES  (B_ * TILES_PER_B)   // 12500
#define NCTA         296       // 2 CTAs per SM

// SMEM byte offsets (per CTA, 2 CTAs/SM)
#define SM_BH    0             // W fp16 panel: 64 x 320B = 20480
#define SM_A     20480         // A fp16 panel: 64 x 320B = 20480
#define SM_RAW   40960         // 320 lines x 64B = 20480
#define SM_OUT   61440         // 64 x 68 x 4B = 17408
#define SM_CTRL  78848
#define SM_TOTAL 78864

#define OUT_PITCH 68

// Global scratch
__device__ __align__(128) __half g_xh[(size_t)B_ * E_ * C_IN_];  // (B,E,C) fp16
__device__ int g_ctr;

// ---------------------------------------------------------------------------
// helpers
// ---------------------------------------------------------------------------
__device__ __forceinline__ uint32_t smem_u32(const void* p) {
    uint32_t a;
    asm("{ .reg .u64 t; cvta.to.shared.u64 t, %1; cvt.u32.u64 %0, t; }" : "=r"(a) : "l"(p));
    return a;
}
__device__ __forceinline__ int swzc(int kc, int row) {
    return (kc < 16) ? (kc ^ (row & 7)) : (16 + ((kc - 16) ^ (row & 3)));
}
__device__ __forceinline__ void ldm_x4(uint32_t* r, uint32_t addr) {
    asm volatile("ldmatrix.sync.aligned.m8n8.x4.shared.b16 {%0,%1,%2,%3}, [%4];"
        : "=r"(r[0]), "=r"(r[1]), "=r"(r[2]), "=r"(r[3]) : "r"(addr));
}
__device__ __forceinline__ void mma16816(float* d, const uint32_t* a, const uint32_t* b) {
    asm volatile(
        "mma.sync.aligned.m16n8k16.row.col.f32.f16.f16.f32 "
        "{%0,%1,%2,%3}, {%4,%5,%6,%7}, {%8,%9}, {%0,%1,%2,%3};"
        : "+f"(d[0]), "+f"(d[1]), "+f"(d[2]), "+f"(d[3])
        : "r"(a[0]), "r"(a[1]), "r"(a[2]), "r"(a[3]), "r"(b[0]), "r"(b[1]));
}
__device__ __forceinline__ void cp_async8(uint32_t smem_addr, const void* gptr) {
    asm volatile("cp.async.ca.shared.global [%0], [%1], 8;"
                 :: "r"(smem_addr), "l"(gptr) : "memory");
}

// ---------------------------------------------------------------------------
// Kernel 1: transpose x (B,C,E) fp32 -> g_xh (B,E,C) fp16
// ---------------------------------------------------------------------------
__global__ void __launch_bounds__(256) transpose_x(const float* __restrict__ x) {
    if (blockIdx.x == 0 && blockIdx.y == 0 && threadIdx.x == 0) g_ctr = 0;
    __shared__ float tile[32][33];
    const int b  = blockIdx.y;
    const int e0 = blockIdx.x * 32;
    const int tx = threadIdx.x & 31;
    const int ty = threadIdx.x >> 5;
    #pragma unroll
    for (int i = 0; i < 4; i++) {
        const int c = ty + i * 8;
        tile[c][tx] = x[((size_t)b * C_IN_ + c) * E_ + e0 + tx];
    }
    __syncthreads();
    #pragma unroll
    for (int i = 0; i < 4; i++) {
        const int e = ty + i * 8;
        g_xh[((size_t)b * E_ + e0 + e) * C_IN_ + tx] = __float2half_rn(tile[tx][e]);
    }
}

// ---------------------------------------------------------------------------
// Kernel 2: persistent gather(cp.async fp16) + half2 combine + HMMA + epilogue
//   64-edge tiles, 512 threads, 2 CTAs/SM. 16 warps = 4m x 4n (warp 16m x 16n)
// ---------------------------------------------------------------------------
__global__ void __launch_bounds__(NTHR, 2)
meshconv_kernel(const int*   __restrict__ Gi,
                const float* __restrict__ W,
                const float* __restrict__ bias,
                float*       __restrict__ out) {
    extern __shared__ __align__(1024) unsigned char smem[];
    const uint32_t sbase = smem_u32(smem);
    int* s_next = (int*)(smem + SM_CTRL);
    float* s_out = (float*)(smem + SM_OUT);

    const int t   = threadIdx.x;
    const int w   = t >> 5;
    const int l   = t & 31;
    const int sub = (l >> 3);      // 0..3 : line within warp group
    const int seg = l & 7;         // 0..7 : 8B segment within 64B line

    // --- W fp16 panel built per CTA from global W ---------------------------
    #pragma unroll
    for (int r = 0; r < 20; r++) {
        const int i   = t + r * NTHR;          // 0..10239
        const int o   = i / CKDIM;
        const int rem = i - o * CKDIM;
        const int c   = rem / KK_;
        const int j   = rem - c * KK_;
        const int k   = j * 32 + c;
        const int kc  = k >> 3;
        const int ki  = k & 7;
        const uint32_t off = (uint32_t)((o * NCH + swzc(kc, o)) * 16 + ki * 2);
        *reinterpret_cast<__half*>(smem + SM_BH + off) = __float2half_rn(W[i]);
    }

    // --- GEMM geometry: warp = 16m x 16n ------------------------------------
    const int m0 = (w & 3) * 16;
    const int n0 = (w >> 2) * 16;
    const int mrA   = ((l >> 3) & 1) * 8 + (l & 7);
    const int kselA = (l >> 4);
    const int nrB   = ((l >> 4) & 1) * 8 + (l & 7);
    const int kselB = ((l >> 3) & 1);
    float bn[2][2];
    #pragma unroll
    for (int g = 0; g < 2; g++) {
        const int n = n0 + g * 8 + (l & 3) * 2;
        bn[g][0] = __ldg(&bias[n]);
        bn[g][1] = __ldg(&bias[n + 1]);
    }

    auto grab = [&](void) { if (t == 0) *s_next = atomicAdd(&g_ctr, 1); };

    int gi[5];
    auto gi_load = [&](int tile) {
        const int b = tile / TILES_PER_B;
        const int e_base = (tile - b * TILES_PER_B) * TILE_M;
        const int* GiB = Gi + (size_t)b * E_ * KK_ + (size_t)e_base * KK_;
        #pragma unroll
        for (int i = 0; i < 5; i++) {
            gi[i] = GiB[(w * 4 + sub) + i * 64];   // 320 lines per tile
        }
    };
    auto gather_issue = [&](int tile) {
        const int b = tile / TILES_PER_B;
        const __half* xb = g_xh + (size_t)b * E_ * C_IN_;
        #pragma unroll
        for (int i = 0; i < 5; i++) {
            const int line  = (w * 4 + sub) + i * 64;
            const int chunk = seg ^ (line & 7);
            cp_async8(sbase + SM_RAW + (uint32_t)(line * 64 + chunk * 8),
                      xb + (size_t)gi[i] * C_IN_ + seg * 4);
        }
        asm volatile("cp.async.commit_group;" ::: "memory");
    };
    auto combine = [&](void) {
        const int e_loc = t >> 3;      // 0..63
        const int oct   = t & 7;       // channels oct*4 .. oct*4+3
        __half2 f[KK_][2];
        #pragma unroll
        for (int j = 0; j < KK_; j++) {
            const int line  = e_loc * KK_ + j;
            const int chunk = oct ^ (line & 7);
            const uint2 v = *(const uint2*)(smem + SM_RAW + line * 64 + chunk * 8);
            f[j][0] = *reinterpret_cast<const __half2*>(&v.x);
            f[j][1] = *reinterpret_cast<const __half2*>(&v.y);
        }
        #pragma unroll
        for (int j = 0; j < KK_; j++) {
            __half2 g0, g1;
            switch (j) {
                case 0: g0 = f[0][0];                          g1 = f[0][1]; break;
                case 1: g0 = __hadd2(f[1][0], f[3][0]);        g1 = __hadd2(f[1][1], f[3][1]); break;
                case 2: g0 = __hadd2(f[2][0], f[4][0]);        g1 = __hadd2(f[2][1], f[4][1]); break;
                case 3: g0 = __habs2(__hsub2(f[1][0], f[3][0])); g1 = __habs2(__hsub2(f[1][1], f[3][1])); break;
                default: g0 = __habs2(__hsub2(f[2][0], f[4][0])); g1 = __habs2(__hsub2(f[2][1], f[4][1])); break;
            }
            const int kc = j * 4 + (oct >> 1);
            const uint32_t off = (uint32_t)((e_loc * NCH + swzc(kc, e_loc)) * 16
                                            + (oct & 1) * 8);
            uint2 v;
            v.x = *reinterpret_cast<uint32_t*>(&g0);
            v.y = *reinterpret_cast<uint32_t*>(&g1);
            *(uint2*)(smem + SM_A + off) = v;
        }
    };
    auto gemm_epilogue = [&](int tile) {
        float acc[2][4] = {{0.f}};
        #pragma unroll
        for (int ks = 0; ks < 10; ks++) {
            uint32_t a4[4], b4[4];
            {
                const int kc = ks * 2 + kselA;
                const int r  = m0 + mrA;
                ldm_x4(a4, sbase + SM_A + (uint32_t)((r * NCH + swzc(kc, r)) * 16));
            }
            {
                const int kc = ks * 2 + kselB;
                const int r  = n0 + nrB;
                ldm_x4(b4, sbase + SM_BH + (uint32_t)((r * NCH + swzc(kc, r)) * 16));
            }
            mma16816(acc[0], a4, b4);
            mma16816(acc[1], a4, b4 + 2);
        }
        // stage into s_out[o][e] (+bias) — bank-conflict-free
        const int b = tile / TILES_PER_B;
        const int e_base = (tile - b * TILES_PER_B) * TILE_M;
        const int r = m0 + (l >> 2);
        #pragma unroll
        for (int g = 0; g < 2; g++) {
            const int n = n0 + g * 8 + (l & 3) * 2;
            s_out[n * OUT_PITCH + r]           = acc[g][0] + bn[g][0];
            s_out[(n + 1) * OUT_PITCH + r]     = acc[g][1] + bn[g][1];
            s_out[n * OUT_PITCH + r + 8]       = acc[g][2] + bn[g][0];
            s_out[(n + 1) * OUT_PITCH + r + 8] = acc[g][3] + bn[g][1];
        }
        __syncthreads();
        // coalesced stores: thread -> (o = t>>3, 8-float chunk = t&7)
        {
            const int o   = t >> 3;
            const int ch8 = t & 7;
            float* orow = out + ((size_t)(b * C_OUT_ + o)) * E_ + e_base + ch8 * 8;
            const float* srow = s_out + o * OUT_PITCH + ch8 * 8;
            *(float4*)(orow)     = make_float4(srow[0], srow[1], srow[2], srow[3]);
            *(float4*)(orow + 4) = make_float4(srow[4], srow[5], srow[6], srow[7]);
        }
    };

    // --- prologue ------------------------------------------------------------
    grab();
    __syncthreads();                 // W panel visible; s_next ready
    int cur = *s_next;               // every CTA gets >= 1 tile (12500 > 296)
    gi_load(cur);
    gather_issue(cur);
    asm volatile("cp.async.wait_group 0;" ::: "memory");
    grab();
    __syncthreads();
    int nxt = *s_next;
    combine();
    if (nxt < TOTAL_TILES) gi_load(nxt);
    __syncthreads();

    // --- main pipelined loop -------------------------------------------------
    for (;;) {
        const bool have = (nxt < TOTAL_TILES);
        if (have) gather_issue(nxt);          // overlaps GEMM
        grab();
        gemm_epilogue(cur);                   // contains one sync
        if (!have) break;
        asm volatile("cp.async.wait_group 0;" ::: "memory");
        __syncthreads();                      // raw ready; s_out consumed
        const int nnxt = *s_next;
        if (nnxt < TOTAL_TILES) gi_load(nnxt);
        combine();
        __syncthreads();                      // A panel ready
        cur = nxt;
        nxt = nnxt;
    }
}

// ---------------------------------------------------------------------------
extern "C" void kernel_launch(void* const* d_in, const int* in_sizes, int n_in,
                              void* d_out, int out_size) {
    const float* x    = (const float*)d_in[0];
    const int*   Gi   = (const int*)  d_in[1];
    const float* W    = (const float*)d_in[2];
    const float* bias = (const float*)d_in[3];
    float*       out  = (float*)d_out;

    transpose_x<<<dim3(E_ / 32, B_), 256>>>(x);

    cudaFuncSetAttribute(meshconv_kernel,
                         cudaFuncAttributeMaxDynamicSharedMemorySize, SM_TOTAL);
    meshconv_kernel<<<NCTA, NTHR, SM_TOTAL>>>(Gi, W, bias, out);
}

// round 12
// speedup vs baseline: 1.9398x; 1.9398x over previous
#include <cuda_runtime.h>
#include <cuda_fp16.h>
#include <cstdint>

// Problem constants
#define B_      4
#define C_IN_   32
#define C_OUT_  64
#define E_      200000
#define KK_     5
#define CKDIM   160
#define TILE_M  128
#define NTHR    512
#define NCH     20             // 16B chunks per A/B row (160 fp16 k-values)

#define TILES_PER_B  1563      // ceil(200000/128)
#define TOTAL_TILES  (B_ * TILES_PER_B)   // 6252
#define NCTA         296       // 2 CTAs per SM

// SMEM byte offsets (per CTA; 2 CTAs/SM => total 2 x 100KB)
#define SM_BH    0             // W fp16 panel: 64 x 320B = 20480
#define SM_A     20480         // A fp16 panel: 128 x 320B = 40960
#define SM_RAW   61440         // 640 lines x 64B = 40960
#define SM_CTRL  102400
#define SM_TOTAL 102416

// Global scratch
__device__ __align__(128) __half g_xh[(size_t)B_ * E_ * C_IN_];  // (B,E,C) fp16
__device__ int g_ctr;

// ---------------------------------------------------------------------------
// helpers
// ---------------------------------------------------------------------------
__device__ __forceinline__ uint32_t smem_u32(const void* p) {
    uint32_t a;
    asm("{ .reg .u64 t; cvta.to.shared.u64 t, %1; cvt.u32.u64 %0, t; }" : "=r"(a) : "l"(p));
    return a;
}
__device__ __forceinline__ int swzc(int kc, int row) {
    return (kc < 16) ? (kc ^ (row & 7)) : (16 + ((kc - 16) ^ (row & 3)));
}
// raw-line chunk swizzle (64B lines, 4 x 16B chunks)
__device__ __forceinline__ int rawch(int seg, int line) {
    return seg ^ ((line ^ (line >> 2)) & 3);
}
__device__ __forceinline__ void ldm_x4(uint32_t* r, uint32_t addr) {
    asm volatile("ldmatrix.sync.aligned.m8n8.x4.shared.b16 {%0,%1,%2,%3}, [%4];"
        : "=r"(r[0]), "=r"(r[1]), "=r"(r[2]), "=r"(r[3]) : "r"(addr));
}
__device__ __forceinline__ void mma16816(float* d, const uint32_t* a, const uint32_t* b) {
    asm volatile(
        "mma.sync.aligned.m16n8k16.row.col.f32.f16.f16.f32 "
        "{%0,%1,%2,%3}, {%4,%5,%6,%7}, {%8,%9}, {%0,%1,%2,%3};"
        : "+f"(d[0]), "+f"(d[1]), "+f"(d[2]), "+f"(d[3])
        : "r"(a[0]), "r"(a[1]), "r"(a[2]), "r"(a[3]), "r"(b[0]), "r"(b[1]));
}
__device__ __forceinline__ void cp_async16(uint32_t smem_addr, const void* gptr) {
    asm volatile("cp.async.cg.shared.global [%0], [%1], 16;"
                 :: "r"(smem_addr), "l"(gptr) : "memory");
}

// ---------------------------------------------------------------------------
// Kernel 1: transpose x (B,C,E) fp32 -> g_xh (B,E,C) fp16
// ---------------------------------------------------------------------------
__global__ void __launch_bounds__(256) transpose_x(const float* __restrict__ x) {
    if (blockIdx.x == 0 && blockIdx.y == 0 && threadIdx.x == 0) g_ctr = 0;
    __shared__ float tile[32][33];
    const int b  = blockIdx.y;
    const int e0 = blockIdx.x * 32;
    const int tx = threadIdx.x & 31;
    const int ty = threadIdx.x >> 5;
    #pragma unroll
    for (int i = 0; i < 4; i++) {
        const int c = ty + i * 8;
        tile[c][tx] = x[((size_t)b * C_IN_ + c) * E_ + e0 + tx];
    }
    __syncthreads();
    #pragma unroll
    for (int i = 0; i < 4; i++) {
        const int e = ty + i * 8;
        g_xh[((size_t)b * E_ + e0 + e) * C_IN_ + tx] = __float2half_rn(tile[tx][e]);
    }
}

// ---------------------------------------------------------------------------
struct TileCtx { int b, e_base; };
__device__ __forceinline__ TileCtx decode_tile(int tile) {
    TileCtx tc;
    tc.b = tile / TILES_PER_B;
    tc.e_base = (tile - tc.b * TILES_PER_B) * TILE_M;
    return tc;
}

// ---------------------------------------------------------------------------
// Kernel 2: persistent gather(fp16 cp.async) + half2 combine + HMMA + direct
//   epilogue. TILE_M=128, 512 threads, 2 CTAs/SM, 2 syncs per tile.
//   16 warps = 4 m-groups x 4 n-groups (warp tile 32m x 16n).
// ---------------------------------------------------------------------------
__global__ void __launch_bounds__(NTHR, 2)
meshconv_kernel(const int*   __restrict__ Gi,
                const float* __restrict__ W,
                const float* __restrict__ bias,
                float*       __restrict__ out) {
    extern __shared__ __align__(1024) unsigned char smem[];
    const uint32_t sbase = smem_u32(smem);
    int* s_next = (int*)(smem + SM_CTRL);

    const int t    = threadIdx.x;
    const int w    = t >> 5;
    const int l    = t & 31;
    const int lsub = l >> 2;       // 0..7 : line slot within warp
    const int seg  = l & 3;        // 0..3 : 16B segment within 64B line

    // --- W fp16 panel built per CTA from global W (L2-hot) ------------------
    #pragma unroll
    for (int r = 0; r < 20; r++) {
        const int i   = t + r * NTHR;          // 0..10239
        const int o   = i / CKDIM;
        const int rem = i - o * CKDIM;
        const int c   = rem / KK_;
        const int j   = rem - c * KK_;
        const int k   = j * 32 + c;
        const int kc  = k >> 3;
        const int ki  = k & 7;
        const uint32_t off = (uint32_t)((o * NCH + swzc(kc, o)) * 16 + ki * 2);
        *reinterpret_cast<__half*>(smem + SM_BH + off) = __float2half_rn(W[i]);
    }

    // --- GEMM geometry: warp = 32m x 16n ------------------------------------
    const int m0 = (w & 3) * 32;
    const int n0 = (w >> 2) * 16;
    const int mrA   = ((l >> 3) & 1) * 8 + (l & 7);
    const int kselA = (l >> 4);
    const int nrB   = ((l >> 4) & 1) * 8 + (l & 7);
    const int kselB = (l >> 3) & 1;
    float bn[2][2];
    #pragma unroll
    for (int g = 0; g < 2; g++) {
        const int n = n0 + g * 8 + (l & 3) * 2;
        bn[g][0] = __ldg(&bias[n]);
        bn[g][1] = __ldg(&bias[n + 1]);
    }

    auto grab = [&](void) { if (t == 0) *s_next = atomicAdd(&g_ctr, 1); };

    int gi[5];
    auto gi_load = [&](int tile) {
        const TileCtx tc = decode_tile(tile);
        const int* GiB = Gi + (size_t)tc.b * E_ * KK_ + (size_t)tc.e_base * KK_;
        const int lim = (E_ - tc.e_base) * KK_;          // 640 except tail (320)
        #pragma unroll
        for (int i = 0; i < 5; i++) {
            const int line = (w * 8 + lsub) + i * 128;   // 0..639
            gi[i] = (line < lim) ? GiB[line] : 0;
        }
    };
    auto gather_issue = [&](int tile) {
        const TileCtx tc = decode_tile(tile);
        const __half* xb = g_xh + (size_t)tc.b * E_ * C_IN_;
        #pragma unroll
        for (int i = 0; i < 5; i++) {
            const int line  = (w * 8 + lsub) + i * 128;
            const int chunk = rawch(seg, line);
            cp_async16(sbase + SM_RAW + (uint32_t)(line * 64 + chunk * 16),
                       xb + (size_t)gi[i] * C_IN_ + seg * 8);
        }
        asm volatile("cp.async.commit_group;" ::: "memory");
    };
    auto combine = [&](void) {
        const int e_loc = t >> 2;      // 0..127
        const int quad  = t & 3;       // channels quad*8 .. quad*8+7 (16B fp16)
        uint4 fr[KK_];
        #pragma unroll
        for (int j = 0; j < KK_; j++) {
            const int line  = e_loc * KK_ + j;
            const int chunk = rawch(quad, line);
            fr[j] = *(const uint4*)(smem + SM_RAW + line * 64 + chunk * 16);
        }
        const __half2* f1 = (const __half2*)&fr[1];
        const __half2* f2 = (const __half2*)&fr[2];
        const __half2* f3 = (const __half2*)&fr[3];
        const __half2* f4 = (const __half2*)&fr[4];
        uint4 gv[KK_];
        gv[0] = fr[0];
        __half2* g1 = (__half2*)&gv[1];
        __half2* g2 = (__half2*)&gv[2];
        __half2* g3 = (__half2*)&gv[3];
        __half2* g4 = (__half2*)&gv[4];
        #pragma unroll
        for (int p = 0; p < 4; p++) {
            g1[p] = __hadd2(f1[p], f3[p]);
            g2[p] = __hadd2(f2[p], f4[p]);
            g3[p] = __habs2(__hsub2(f1[p], f3[p]));
            g4[p] = __habs2(__hsub2(f2[p], f4[p]));
        }
        #pragma unroll
        for (int j = 0; j < KK_; j++) {
            const int kc = j * 4 + quad;
            const uint32_t off = (uint32_t)((e_loc * NCH + swzc(kc, e_loc)) * 16);
            *(uint4*)(smem + SM_A + off) = gv[j];
        }
    };
    auto gemm_store = [&](int tile) {
        float acc[4][4] = {{0.f}};
        #pragma unroll
        for (int ks = 0; ks < 10; ks++) {
            uint32_t alo[4], ahi[4], b4[4];
            {
                const int kc = ks * 2 + kselA;
                const int rl = m0 + mrA;
                const int rh = m0 + 16 + mrA;
                ldm_x4(alo, sbase + SM_A + (uint32_t)((rl * NCH + swzc(kc, rl)) * 16));
                ldm_x4(ahi, sbase + SM_A + (uint32_t)((rh * NCH + swzc(kc, rh)) * 16));
            }
            {
                const int kc = ks * 2 + kselB;
                const int rb = n0 + nrB;
                ldm_x4(b4, sbase + SM_BH + (uint32_t)((rb * NCH + swzc(kc, rb)) * 16));
            }
            mma16816(acc[0], alo, b4);
            mma16816(acc[1], alo, b4 + 2);
            mma16816(acc[2], ahi, b4);
            mma16816(acc[3], ahi, b4 + 2);
        }
        // direct stores: each instr covers 8 consecutive e per o-row (full 32B sectors)
        const TileCtx tc = decode_tile(tile);
        const int r  = m0 + (l >> 2);
        const int e1 = tc.e_base + r;
        #pragma unroll
        for (int g = 0; g < 2; g++) {
            const int n = n0 + g * 8 + (l & 3) * 2;
            float* o0 = out + ((size_t)(tc.b * C_OUT_ + n)) * E_;
            float* o1 = out + ((size_t)(tc.b * C_OUT_ + n + 1)) * E_;
            if (e1 < E_) {
                o0[e1]      = acc[g][0] + bn[g][0];
                o1[e1]      = acc[g][1] + bn[g][1];
                o0[e1 + 8]  = acc[g][2] + bn[g][0];
                o1[e1 + 8]  = acc[g][3] + bn[g][1];
            }
            if (e1 + 16 < E_) {
                o0[e1 + 16] = acc[2 + g][0] + bn[g][0];
                o1[e1 + 16] = acc[2 + g][1] + bn[g][1];
                o0[e1 + 24] = acc[2 + g][2] + bn[g][0];
                o1[e1 + 24] = acc[2 + g][3] + bn[g][1];
            }
        }
    };

    // --- prologue ------------------------------------------------------------
    grab();
    __syncthreads();                 // W panel visible; s_next ready
    int cur = *s_next;               // every CTA gets >= 1 tile (6252 > 296)
    gi_load(cur);
    gather_issue(cur);
    grab();
    asm volatile("cp.async.wait_group 0;" ::: "memory");
    __syncthreads();                 // raw ready; s_next visible
    int nxt = *s_next;
    if (nxt < TOTAL_TILES) gi_load(nxt);
    combine();                       // RAW -> A (tile cur)
    __syncthreads();                 // A ready

    // --- main loop: 2 syncs per tile ----------------------------------------
    for (;;) {
        const bool have = (nxt < TOTAL_TILES);
        if (have) gather_issue(nxt);          // cp.async overlaps GEMM
        grab();
        gemm_store(cur);                      // reads A; direct gmem stores
        if (!have) break;
        asm volatile("cp.async.wait_group 0;" ::: "memory");
        __syncthreads();                      // A free; raw ready; s_next visible
        const int nnxt = *s_next;
        if (nnxt < TOTAL_TILES) gi_load(nnxt);// LDG overlaps combine
        combine();                            // RAW -> A (tile nxt)
        __syncthreads();                      // A ready
        cur = nxt;
        nxt = nnxt;
    }
}

// ---------------------------------------------------------------------------
extern "C" void kernel_launch(void* const* d_in, const int* in_sizes, int n_in,
                              void* d_out, int out_size) {
    const float* x    = (const float*)d_in[0];
    const int*   Gi   = (const int*)  d_in[1];
    const float* W    = (const float*)d_in[2];
    const float* bias = (const float*)d_in[3];
    float*       out  = (float*)d_out;

    transpose_x<<<dim3(E_ / 32, B_), 256>>>(x);

    cudaFuncSetAttribute(meshconv_kernel,
                         cudaFuncAttributeMaxDynamicSharedMemorySize, SM_TOTAL);
    meshconv_kernel<<<NCTA, NTHR, SM_TOTAL>>>(Gi, W, bias, out);
}

// round 14
// speedup vs baseline: 2.0278x; 1.0454x over previous
#include <cuda_runtime.h>
#include <cuda_fp16.h>
#include <cstdint>

// Problem constants
#define B_      4
#define C_IN_   32
#define C_OUT_  64
#define E_      200000
#define KK_     5
#define CKDIM   160
#define TILE_M  128
#define NTHR    512
#define NCH     20             // 16B chunks per A/B row (160 fp16 k-values)

#define TILES_PER_B  1563
#define TOTAL_TILES  (B_ * TILES_PER_B)   // 6252
#define NCTA         148

// SMEM layout (1 CTA/SM)
#define SM_BH    0             // W fp16 panel: 64 x 320B = 20480
#define SM_A0    20480         // A panel buf0: 128 x 320B = 40960
#define SM_A1    61440
#define SM_RAW0  102400        // raw gather buf0: 640 x 64B = 40960
#define SM_RAW1  143360
#define SM_CTRL  184320        // [0]=init tile, [1..2]=s_pnext, [3..4]=s_tile
#define SM_TOTAL 184384

// Named barrier ids
#define BAR_READY0 1
#define BAR_READY1 2
#define BAR_FREE0  3
#define BAR_FREE1  4
#define BAR_PROD   5

// Global scratch
__device__ __align__(128) __half g_xh[(size_t)B_ * E_ * C_IN_];  // (B,E,C) fp16
__device__ int g_ctr;

// ---------------------------------------------------------------------------
// helpers
// ---------------------------------------------------------------------------
__device__ __forceinline__ uint32_t smem_u32(const void* p) {
    uint32_t a;
    asm("{ .reg .u64 t; cvta.to.shared.u64 t, %1; cvt.u32.u64 %0, t; }" : "=r"(a) : "l"(p));
    return a;
}
__device__ __forceinline__ int swzc(int kc, int row) {
    return (kc < 16) ? (kc ^ (row & 7)) : (16 + ((kc - 16) ^ (row & 3)));
}
__device__ __forceinline__ int rawch(int seg, int line) {
    return seg ^ ((line ^ (line >> 2)) & 3);
}
__device__ __forceinline__ void ldm_x4(uint32_t* r, uint32_t addr) {
    asm volatile("ldmatrix.sync.aligned.m8n8.x4.shared.b16 {%0,%1,%2,%3}, [%4];"
        : "=r"(r[0]), "=r"(r[1]), "=r"(r[2]), "=r"(r[3]) : "r"(addr));
}
__device__ __forceinline__ void mma16816(float* d, const uint32_t* a, const uint32_t* b) {
    asm volatile(
        "mma.sync.aligned.m16n8k16.row.col.f32.f16.f16.f32 "
        "{%0,%1,%2,%3}, {%4,%5,%6,%7}, {%8,%9}, {%0,%1,%2,%3};"
        : "+f"(d[0]), "+f"(d[1]), "+f"(d[2]), "+f"(d[3])
        : "r"(a[0]), "r"(a[1]), "r"(a[2]), "r"(a[3]), "r"(b[0]), "r"(b[1]));
}
__device__ __forceinline__ void cp_async16(uint32_t smem_addr, const void* gptr) {
    asm volatile("cp.async.cg.shared.global [%0], [%1], 16;"
                 :: "r"(smem_addr), "l"(gptr) : "memory");
}
__device__ __forceinline__ void bar_sync(int id, int cnt) {
    asm volatile("bar.sync %0, %1;" :: "r"(id), "r"(cnt) : "memory");
}
__device__ __forceinline__ void bar_arrive(int id, int cnt) {
    asm volatile("bar.arrive %0, %1;" :: "r"(id), "r"(cnt) : "memory");
}

// ---------------------------------------------------------------------------
// Kernel 1: transpose x (B,C,E) fp32 -> g_xh (B,E,C) fp16. 64e x 32c tiles.
// ---------------------------------------------------------------------------
__global__ void __launch_bounds__(256) transpose_x(const float* __restrict__ x) {
    if (blockIdx.x == 0 && blockIdx.y == 0 && threadIdx.x == 0) g_ctr = 0;
    __shared__ float tile[32][65];
    const int b  = blockIdx.y;
    const int e0 = blockIdx.x * 64;
    const int t  = threadIdx.x;
    // read: thread -> (c = t>>3, e-oct = (t&7)*8); 2 float4 per thread
    {
        const int c  = t >> 3;
        const int eo = (t & 7) * 8;
        const float4 v0 = *(const float4*)(x + ((size_t)b * C_IN_ + c) * E_ + e0 + eo);
        const float4 v1 = *(const float4*)(x + ((size_t)b * C_IN_ + c) * E_ + e0 + eo + 4);
        tile[c][eo + 0] = v0.x; tile[c][eo + 1] = v0.y;
        tile[c][eo + 2] = v0.z; tile[c][eo + 3] = v0.w;
        tile[c][eo + 4] = v1.x; tile[c][eo + 5] = v1.y;
        tile[c][eo + 6] = v1.z; tile[c][eo + 7] = v1.w;
    }
    __syncthreads();
    // write: thread -> (e = t>>2, c-oct = t&3); pack 8 halves -> one uint4
    {
        const int e    = t >> 2;
        const int coct = t & 3;
        uint4 o;
        uint32_t* op = (uint32_t*)&o;
        #pragma unroll
        for (int p = 0; p < 4; p++) {
            const float a = tile[coct * 8 + p * 2][e];
            const float c = tile[coct * 8 + p * 2 + 1][e];
            __half2 h = __floats2half2_rn(a, c);
            op[p] = *reinterpret_cast<uint32_t*>(&h);
        }
        *(uint4*)(g_xh + ((size_t)b * E_ + e0 + e) * C_IN_ + coct * 8) = o;
    }
}

// ---------------------------------------------------------------------------
struct TileCtx { int b, e_base; };
__device__ __forceinline__ TileCtx decode_tile(int tile) {
    TileCtx tc;
    tc.b = tile / TILES_PER_B;
    tc.e_base = (tile - tc.b * TILES_PER_B) * TILE_M;
    return tc;
}

// ---------------------------------------------------------------------------
// Kernel 2: warp-specialized persistent kernel.
//   Warps 0-7  (t<256):  consumer — HMMA GEMM + direct stores.
//   Warps 8-15 (t>=256): producer — Gi + cp.async gather + half2 combine.
//   Double-buffered A panels and RAW buffers; named-barrier handshake.
// ---------------------------------------------------------------------------
__global__ void __launch_bounds__(NTHR, 1)
meshconv_kernel(const int*   __restrict__ Gi,
                const float* __restrict__ W,
                const float* __restrict__ bias,
                float*       __restrict__ out) {
    extern __shared__ __align__(1024) unsigned char smem[];
    const uint32_t sbase = smem_u32(smem);
    int* s_ctrl = (int*)(smem + SM_CTRL);   // [0] init, [1..2] pnext, [3..4] tile

    const int t = threadIdx.x;

    // --- W fp16 panel built by all threads ----------------------------------
    #pragma unroll
    for (int r = 0; r < 20; r++) {
        const int i   = t + r * NTHR;
        const int o   = i / CKDIM;
        const int rem = i - o * CKDIM;
        const int c   = rem / KK_;
        const int j   = rem - c * KK_;
        const int k   = j * 32 + c;
        const uint32_t off = (uint32_t)((o * NCH + swzc(k >> 3, o)) * 16 + (k & 7) * 2);
        *reinterpret_cast<__half*>(smem + SM_BH + off) = __float2half_rn(W[i]);
    }
    if (t == 0) s_ctrl[0] = atomicAdd(&g_ctr, 1);
    __syncthreads();

    const uint32_t Abase[2]   = { sbase + SM_A0, sbase + SM_A1 };
    const uint32_t Rawbase[2] = { sbase + SM_RAW0, sbase + SM_RAW1 };
    const int ready_id[2] = { BAR_READY0, BAR_READY1 };
    const int free_id[2]  = { BAR_FREE0,  BAR_FREE1  };

    if (t >= 256) {
        // =================== PRODUCER (warps 8-15) ==========================
        const int pt   = t - 256;
        const int pw   = pt >> 5;
        const int pl   = pt & 31;
        const int lsub = pl >> 2;       // 0..7
        const int seg  = pl & 3;        // 0..3

        int tile = s_ctrl[0];
        int buf  = 0;
        int n    = 0;
        for (;;) {
            if (tile >= TOTAL_TILES) {
                if (n >= 2) bar_sync(free_id[buf], NTHR);
                if (pt == 0) s_ctrl[3 + buf] = -1;
                bar_arrive(ready_id[buf], NTHR);
                break;
            }
            if (n >= 2) bar_sync(free_id[buf], NTHR);   // A[buf]+RAW[buf] free

            // gather: cp.async fp16 lines into RAW[buf]
            {
                const TileCtx tc = decode_tile(tile);
                const int* GiB = Gi + (size_t)tc.b * E_ * KK_ + (size_t)tc.e_base * KK_;
                const int lim  = (E_ - tc.e_base) * KK_;
                const __half* xb = g_xh + (size_t)tc.b * E_ * C_IN_;
                #pragma unroll
                for (int i = 0; i < 10; i++) {
                    const int line = (pw * 8 + lsub) + i * 64;
                    const int gidx = (line < lim) ? GiB[line] : 0;
                    const int chunk = rawch(seg, line);
                    cp_async16(Rawbase[buf] + (uint32_t)(line * 64 + chunk * 16),
                               xb + (size_t)gidx * C_IN_ + seg * 8);
                }
                asm volatile("cp.async.commit_group;" ::: "memory");
            }
            if (pt == 0) s_ctrl[1 + buf] = atomicAdd(&g_ctr, 1);
            asm volatile("cp.async.wait_group 0;" ::: "memory");
            bar_sync(BAR_PROD, 256);                    // raw + pnext visible

            // combine: 512 slots, 2 per thread
            #pragma unroll
            for (int it = 0; it < 2; it++) {
                const int slot  = pt + it * 256;
                const int e_loc = slot >> 2;
                const int quad  = slot & 3;
                uint4 fr[KK_];
                #pragma unroll
                for (int j = 0; j < KK_; j++) {
                    const int line = e_loc * KK_ + j;
                    fr[j] = *(const uint4*)(smem + (Rawbase[buf] - sbase)
                                            + line * 64 + rawch(quad, line) * 16);
                }
                const __half2* f1 = (const __half2*)&fr[1];
                const __half2* f2 = (const __half2*)&fr[2];
                const __half2* f3 = (const __half2*)&fr[3];
                const __half2* f4 = (const __half2*)&fr[4];
                uint4 gv[KK_];
                gv[0] = fr[0];
                __half2* g1 = (__half2*)&gv[1];
                __half2* g2 = (__half2*)&gv[2];
                __half2* g3 = (__half2*)&gv[3];
                __half2* g4 = (__half2*)&gv[4];
                #pragma unroll
                for (int p = 0; p < 4; p++) {
                    g1[p] = __hadd2(f1[p], f3[p]);
                    g2[p] = __hadd2(f2[p], f4[p]);
                    g3[p] = __habs2(__hsub2(f1[p], f3[p]));
                    g4[p] = __habs2(__hsub2(f2[p], f4[p]));
                }
                #pragma unroll
                for (int j = 0; j < KK_; j++) {
                    const int kc = j * 4 + quad;
                    const uint32_t off = (uint32_t)((e_loc * NCH + swzc(kc, e_loc)) * 16);
                    *(uint4*)(smem + (Abase[buf] - sbase) + off) = gv[j];
                }
            }
            if (pt == 0) s_ctrl[3 + buf] = tile;
            bar_arrive(ready_id[buf], NTHR);            // A[buf] ready
            tile = s_ctrl[1 + buf];
            buf ^= 1;
            n++;
        }
    } else {
        // =================== CONSUMER (warps 0-7) ===========================
        const int cw = t >> 5;
        const int l  = t & 31;
        const int m0 = (cw & 3) * 32;
        const int n0 = (cw >> 2) * 32;
        const int mrA   = ((l >> 3) & 1) * 8 + (l & 7);
        const int kselA = (l >> 4);
        const int nrB   = ((l >> 4) & 1) * 8 + (l & 7);
        const int kselB = (l >> 3) & 1;
        float bn[4][2];
        #pragma unroll
        for (int nb = 0; nb < 4; nb++) {
            const int nn = n0 + nb * 8 + (l & 3) * 2;
            bn[nb][0] = __ldg(&bias[nn]);
            bn[nb][1] = __ldg(&bias[nn + 1]);
        }

        int buf = 0;
        for (;;) {
            bar_sync(ready_id[buf], NTHR);
            const int tile = s_ctrl[3 + buf];
            if (tile < 0) break;

            float acc[2][4][4];
            #pragma unroll
            for (int a = 0; a < 2; a++)
                #pragma unroll
                for (int b2 = 0; b2 < 4; b2++)
                    #pragma unroll
                    for (int v = 0; v < 4; v++) acc[a][b2][v] = 0.f;

            const uint32_t A = Abase[buf];
            #pragma unroll
            for (int ks = 0; ks < 10; ks++) {
                uint32_t alo[4], ahi[4], b0[4], b1[4];
                {
                    const int kc = ks * 2 + kselA;
                    const int rl = m0 + mrA;
                    const int rh = rl + 16;
                    ldm_x4(alo, A + (uint32_t)((rl * NCH + swzc(kc, rl)) * 16));
                    ldm_x4(ahi, A + (uint32_t)((rh * NCH + swzc(kc, rh)) * 16));
                }
                {
                    const int kc = ks * 2 + kselB;
                    const int r0 = n0 + nrB;
                    const int r1 = r0 + 16;
                    ldm_x4(b0, sbase + SM_BH + (uint32_t)((r0 * NCH + swzc(kc, r0)) * 16));
                    ldm_x4(b1, sbase + SM_BH + (uint32_t)((r1 * NCH + swzc(kc, r1)) * 16));
                }
                mma16816(acc[0][0], alo, b0);  mma16816(acc[0][1], alo, b0 + 2);
                mma16816(acc[0][2], alo, b1);  mma16816(acc[0][3], alo, b1 + 2);
                mma16816(acc[1][0], ahi, b0);  mma16816(acc[1][1], ahi, b0 + 2);
                mma16816(acc[1][2], ahi, b1);  mma16816(acc[1][3], ahi, b1 + 2);
            }

            // direct stores (+bias)
            {
                const TileCtx tc = decode_tile(tile);
                const int r = m0 + (l >> 2);
                #pragma unroll
                for (int mb = 0; mb < 2; mb++) {
                    const int e1 = tc.e_base + r + mb * 16;
                    if (e1 < E_) {
                        #pragma unroll
                        for (int nb = 0; nb < 4; nb++) {
                            const int nn = n0 + nb * 8 + (l & 3) * 2;
                            float* o0 = out + ((size_t)(tc.b * C_OUT_ + nn)) * E_;
                            float* o1 = out + ((size_t)(tc.b * C_OUT_ + nn + 1)) * E_;
                            o0[e1]     = acc[mb][nb][0] + bn[nb][0];
                            o1[e1]     = acc[mb][nb][1] + bn[nb][1];
                            o0[e1 + 8] = acc[mb][nb][2] + bn[nb][0];
                            o1[e1 + 8] = acc[mb][nb][3] + bn[nb][1];
                        }
                    }
                }
            }
            bar_arrive(free_id[buf], NTHR);
            buf ^= 1;
        }
    }
}

// ---------------------------------------------------------------------------
extern "C" void kernel_launch(void* const* d_in, const int* in_sizes, int n_in,
                              void* d_out, int out_size) {
    const float* x    = (const float*)d_in[0];
    const int*   Gi   = (const int*)  d_in[1];
    const float* W    = (const float*)d_in[2];
    const float* bias = (const float*)d_in[3];
    float*       out  = (float*)d_out;

    transpose_x<<<dim3(E_ / 64, B_), 256>>>(x);

    cudaFuncSetAttribute(meshconv_kernel,
                         cudaFuncAttributeMaxDynamicSharedMemorySize, SM_TOTAL);
    meshconv_kernel<<<NCTA, NTHR, SM_TOTAL>>>(Gi, W, bias, out);
}

// round 15
// speedup vs baseline: 2.2773x; 1.1230x over previous
#include <cuda_runtime.h>
#include <cuda_fp16.h>
#include <cstdint>

// Problem constants
#define B_      4
#define C_IN_   32
#define C_OUT_  64
#define E_      200000
#define KK_     5
#define CKDIM   160
#define TILE_M  256
#define NTHR    512
#define NCH     20             // 16B chunks per A/B row (160 fp16 k-values)

#define TILES_PER_B  782       // 781 full + 1 tail (64 edges)
#define TOTAL_TILES  (B_ * TILES_PER_B)   // 3128
#define NCTA         148

// SMEM layout (1 CTA/SM)
#define SM_BH    0             // W fp16 panel: 64 x 320B = 20480
#define SM_A0    20480         // A panel buf0: 256 x 320B = 81920
#define SM_A1    102400        // A panel buf1
#define SM_CTRL  184320        // [0]=init tile, [1..2]=pnext, [3..4]=tile
#define SM_TOTAL 184384

// Named barrier ids
#define BAR_READY0 1
#define BAR_READY1 2
#define BAR_FREE0  3
#define BAR_FREE1  4
#define BAR_PROD   5

// Global scratch
__device__ __align__(128) __half g_xh[(size_t)B_ * E_ * C_IN_];  // (B,E,C) fp16
__device__ int g_ctr;

// ---------------------------------------------------------------------------
// helpers
// ---------------------------------------------------------------------------
__device__ __forceinline__ uint32_t smem_u32(const void* p) {
    uint32_t a;
    asm("{ .reg .u64 t; cvta.to.shared.u64 t, %1; cvt.u32.u64 %0, t; }" : "=r"(a) : "l"(p));
    return a;
}
__device__ __forceinline__ int swzc(int kc, int row) {
    return (kc < 16) ? (kc ^ (row & 7)) : (16 + ((kc - 16) ^ (row & 3)));
}
__device__ __forceinline__ void ldm_x4(uint32_t* r, uint32_t addr) {
    asm volatile("ldmatrix.sync.aligned.m8n8.x4.shared.b16 {%0,%1,%2,%3}, [%4];"
        : "=r"(r[0]), "=r"(r[1]), "=r"(r[2]), "=r"(r[3]) : "r"(addr));
}
__device__ __forceinline__ void mma16816(float* d, const uint32_t* a, const uint32_t* b) {
    asm volatile(
        "mma.sync.aligned.m16n8k16.row.col.f32.f16.f16.f32 "
        "{%0,%1,%2,%3}, {%4,%5,%6,%7}, {%8,%9}, {%0,%1,%2,%3};"
        : "+f"(d[0]), "+f"(d[1]), "+f"(d[2]), "+f"(d[3])
        : "r"(a[0]), "r"(a[1]), "r"(a[2]), "r"(a[3]), "r"(b[0]), "r"(b[1]));
}
__device__ __forceinline__ void bar_sync(int id, int cnt) {
    asm volatile("bar.sync %0, %1;" :: "r"(id), "r"(cnt) : "memory");
}
__device__ __forceinline__ void bar_arrive(int id, int cnt) {
    asm volatile("bar.arrive %0, %1;" :: "r"(id), "r"(cnt) : "memory");
}

// ---------------------------------------------------------------------------
// Kernel 1: transpose x (B,C,E) fp32 -> g_xh (B,E,C) fp16. 64e x 32c tiles.
// ---------------------------------------------------------------------------
__global__ void __launch_bounds__(256) transpose_x(const float* __restrict__ x) {
    if (blockIdx.x == 0 && blockIdx.y == 0 && threadIdx.x == 0) g_ctr = 0;
    __shared__ float tile[32][65];
    const int b  = blockIdx.y;
    const int e0 = blockIdx.x * 64;
    const int t  = threadIdx.x;
    {
        const int c  = t >> 3;
        const int eo = (t & 7) * 8;
        const float4 v0 = *(const float4*)(x + ((size_t)b * C_IN_ + c) * E_ + e0 + eo);
        const float4 v1 = *(const float4*)(x + ((size_t)b * C_IN_ + c) * E_ + e0 + eo + 4);
        tile[c][eo + 0] = v0.x; tile[c][eo + 1] = v0.y;
        tile[c][eo + 2] = v0.z; tile[c][eo + 3] = v0.w;
        tile[c][eo + 4] = v1.x; tile[c][eo + 5] = v1.y;
        tile[c][eo + 6] = v1.z; tile[c][eo + 7] = v1.w;
    }
    __syncthreads();
    {
        const int e    = t >> 2;
        const int coct = t & 3;
        uint4 o;
        uint32_t* op = (uint32_t*)&o;
        #pragma unroll
        for (int p = 0; p < 4; p++) {
            const float a = tile[coct * 8 + p * 2][e];
            const float c = tile[coct * 8 + p * 2 + 1][e];
            __half2 h = __floats2half2_rn(a, c);
            op[p] = *reinterpret_cast<uint32_t*>(&h);
        }
        *(uint4*)(g_xh + ((size_t)b * E_ + e0 + e) * C_IN_ + coct * 8) = o;
    }
}

// ---------------------------------------------------------------------------
struct TileCtx { int b, e_base; };
__device__ __forceinline__ TileCtx decode_tile(int tile) {
    TileCtx tc;
    tc.b = tile / TILES_PER_B;
    tc.e_base = (tile - tc.b * TILES_PER_B) * TILE_M;
    return tc;
}

// ---------------------------------------------------------------------------
// Kernel 2: warp-specialized persistent kernel, 256-edge tiles.
//   Warps 0-7  (t<256):  consumer — HMMA (2 m-halves, B-frag reuse) + stores.
//   Warps 8-15 (t>=256): producer — Gi + LDG gather to regs + half2 combine
//                        directly into double-buffered A panels.
// ---------------------------------------------------------------------------
__global__ void __launch_bounds__(NTHR, 1)
meshconv_kernel(const int*   __restrict__ Gi,
                const float* __restrict__ W,
                const float* __restrict__ bias,
                float*       __restrict__ out) {
    extern __shared__ __align__(1024) unsigned char smem[];
    const uint32_t sbase = smem_u32(smem);
    int* s_ctrl = (int*)(smem + SM_CTRL);

    const int t = threadIdx.x;

    // --- W fp16 panel built by all threads ----------------------------------
    #pragma unroll
    for (int r = 0; r < 20; r++) {
        const int i   = t + r * NTHR;
        const int o   = i / CKDIM;
        const int rem = i - o * CKDIM;
        const int c   = rem / KK_;
        const int j   = rem - c * KK_;
        const int k   = j * 32 + c;
        const uint32_t off = (uint32_t)((o * NCH + swzc(k >> 3, o)) * 16 + (k & 7) * 2);
        *reinterpret_cast<__half*>(smem + SM_BH + off) = __float2half_rn(W[i]);
    }
    if (t == 0) s_ctrl[0] = atomicAdd(&g_ctr, 1);
    __syncthreads();

    const uint32_t Aoff[2]  = { SM_A0, SM_A1 };
    const int ready_id[2] = { BAR_READY0, BAR_READY1 };
    const int free_id[2]  = { BAR_FREE0,  BAR_FREE1  };

    if (t >= 256) {
        // =================== PRODUCER (warps 8-15) ==========================
        const int pt    = t - 256;
        const int e_sub = pt >> 2;     // 0..63
        const int quad  = pt & 3;      // channel group (16B of fp16)

        int tile = s_ctrl[0];
        int buf  = 0;
        int n    = 0;
        for (;;) {
            if (tile >= TOTAL_TILES) {
                if (n >= 2) bar_sync(free_id[buf], NTHR);
                if (pt == 0) s_ctrl[3 + buf] = -1;
                bar_arrive(ready_id[buf], NTHR);
                break;
            }
            if (n >= 2) bar_sync(free_id[buf], NTHR);    // A[buf] free

            const TileCtx tc = decode_tile(tile);
            if (pt == 0) s_ctrl[1 + buf] = atomicAdd(&g_ctr, 1);
            const __half* xb = g_xh + (size_t)tc.b * E_ * C_IN_;
            const int* GiB = Gi + ((size_t)tc.b * E_ + tc.e_base) * KK_;

            // Gi for all 4 slots up front (broadcast across 4 lanes)
            int gidx[4][KK_];
            #pragma unroll
            for (int it = 0; it < 4; it++) {
                const int e_loc = it * 64 + e_sub;
                const bool ok = (tc.e_base + e_loc) < E_;
                #pragma unroll
                for (int j = 0; j < KK_; j++)
                    gidx[it][j] = ok ? GiB[e_loc * KK_ + j] : 0;
            }

            // pipelined gather (2-deep) + combine + STS into A[buf]
            uint4 f[2][KK_];
            #pragma unroll
            for (int j = 0; j < KK_; j++)
                f[0][j] = *(const uint4*)(xb + (size_t)gidx[0][j] * C_IN_ + quad * 8);
            #pragma unroll
            for (int j = 0; j < KK_; j++)
                f[1][j] = *(const uint4*)(xb + (size_t)gidx[1][j] * C_IN_ + quad * 8);

            #pragma unroll
            for (int it = 0; it < 4; it++) {
                uint4 fr[KK_];
                #pragma unroll
                for (int j = 0; j < KK_; j++) fr[j] = f[it & 1][j];
                if (it < 2) {
                    #pragma unroll
                    for (int j = 0; j < KK_; j++)
                        f[it & 1][j] = *(const uint4*)(xb + (size_t)gidx[it + 2][j] * C_IN_ + quad * 8);
                }
                const __half2* f1 = (const __half2*)&fr[1];
                const __half2* f2 = (const __half2*)&fr[2];
                const __half2* f3 = (const __half2*)&fr[3];
                const __half2* f4 = (const __half2*)&fr[4];
                uint4 gv[KK_];
                gv[0] = fr[0];
                __half2* g1 = (__half2*)&gv[1];
                __half2* g2 = (__half2*)&gv[2];
                __half2* g3 = (__half2*)&gv[3];
                __half2* g4 = (__half2*)&gv[4];
                #pragma unroll
                for (int p = 0; p < 4; p++) {
                    g1[p] = __hadd2(f1[p], f3[p]);
                    g2[p] = __hadd2(f2[p], f4[p]);
                    g3[p] = __habs2(__hsub2(f1[p], f3[p]));
                    g4[p] = __habs2(__hsub2(f2[p], f4[p]));
                }
                const int e_loc = it * 64 + e_sub;
                #pragma unroll
                for (int j = 0; j < KK_; j++) {
                    const int kc = j * 4 + quad;
                    const uint32_t off = (uint32_t)((e_loc * NCH + swzc(kc, e_loc)) * 16);
                    *(uint4*)(smem + Aoff[buf] + off) = gv[j];
                }
            }
            if (pt == 0) s_ctrl[3 + buf] = tile;
            bar_arrive(ready_id[buf], NTHR);             // A[buf] ready
            bar_sync(BAR_PROD, 256);                     // pnext visible
            tile = s_ctrl[1 + buf];
            buf ^= 1;
            n++;
        }
    } else {
        // =================== CONSUMER (warps 0-7) ===========================
        const int cw = t >> 5;
        const int l  = t & 31;
        const int m0 = (cw & 3) * 32;       // within each 128-edge m-half
        const int n0 = (cw >> 2) * 32;
        const int mrA   = ((l >> 3) & 1) * 8 + (l & 7);
        const int kselA = (l >> 4);
        const int nrB   = ((l >> 4) & 1) * 8 + (l & 7);
        const int kselB = (l >> 3) & 1;
        float bn[4][2];
        #pragma unroll
        for (int nb = 0; nb < 4; nb++) {
            const int nn = n0 + nb * 8 + (l & 3) * 2;
            bn[nb][0] = __ldg(&bias[nn]);
            bn[nb][1] = __ldg(&bias[nn + 1]);
        }

        int buf = 0;
        for (;;) {
            bar_sync(ready_id[buf], NTHR);
            const int tile = s_ctrl[3 + buf];
            if (tile < 0) break;

            float acc[2][2][4][4];   // [m-half][16-row block][n-block][frag]
            #pragma unroll
            for (int a = 0; a < 2; a++)
                #pragma unroll
                for (int b2 = 0; b2 < 2; b2++)
                    #pragma unroll
                    for (int c2 = 0; c2 < 4; c2++)
                        #pragma unroll
                        for (int v = 0; v < 4; v++) acc[a][b2][c2][v] = 0.f;

            const uint32_t A = sbase + Aoff[buf];
            #pragma unroll
            for (int ks = 0; ks < 10; ks++) {
                uint32_t b0[4], b1[4];
                {
                    const int kc = ks * 2 + kselB;
                    const int r0 = n0 + nrB;
                    const int r1 = r0 + 16;
                    ldm_x4(b0, sbase + SM_BH + (uint32_t)((r0 * NCH + swzc(kc, r0)) * 16));
                    ldm_x4(b1, sbase + SM_BH + (uint32_t)((r1 * NCH + swzc(kc, r1)) * 16));
                }
                #pragma unroll
                for (int mh = 0; mh < 2; mh++) {
                    uint32_t alo[4], ahi[4];
                    const int kc = ks * 2 + kselA;
                    const int rl = mh * 128 + m0 + mrA;
                    const int rh = rl + 16;
                    ldm_x4(alo, A + (uint32_t)((rl * NCH + swzc(kc, rl)) * 16));
                    ldm_x4(ahi, A + (uint32_t)((rh * NCH + swzc(kc, rh)) * 16));
                    mma16816(acc[mh][0][0], alo, b0);  mma16816(acc[mh][0][1], alo, b0 + 2);
                    mma16816(acc[mh][0][2], alo, b1);  mma16816(acc[mh][0][3], alo, b1 + 2);
                    mma16816(acc[mh][1][0], ahi, b0);  mma16816(acc[mh][1][1], ahi, b0 + 2);
                    mma16816(acc[mh][1][2], ahi, b1);  mma16816(acc[mh][1][3], ahi, b1 + 2);
                }
            }

            // direct stores (+bias)
            {
                const TileCtx tc = decode_tile(tile);
                #pragma unroll
                for (int mh = 0; mh < 2; mh++) {
                    #pragma unroll
                    for (int mb = 0; mb < 2; mb++) {
                        const int e1 = tc.e_base + mh * 128 + m0 + (l >> 2) + mb * 16;
                        if (e1 < E_) {
                            #pragma unroll
                            for (int nb = 0; nb < 4; nb++) {
                                const int nn = n0 + nb * 8 + (l & 3) * 2;
                                float* o0 = out + ((size_t)(tc.b * C_OUT_ + nn)) * E_;
                                float* o1 = out + ((size_t)(tc.b * C_OUT_ + nn + 1)) * E_;
                                o0[e1]     = acc[mh][mb][nb][0] + bn[nb][0];
                                o1[e1]     = acc[mh][mb][nb][1] + bn[nb][1];
                                o0[e1 + 8] = acc[mh][mb][nb][2] + bn[nb][0];
                                o1[e1 + 8] = acc[mh][mb][nb][3] + bn[nb][1];
                            }
                        }
                    }
                }
            }
            bar_arrive(free_id[buf], NTHR);
            buf ^= 1;
        }
    }
}

// ---------------------------------------------------------------------------
extern "C" void kernel_launch(void* const* d_in, const int* in_sizes, int n_in,
                              void* d_out, int out_size) {
    const float* x    = (const float*)d_in[0];
    const int*   Gi   = (const int*)  d_in[1];
    const float* W    = (const float*)d_in[2];
    const float* bias = (const float*)d_in[3];
    float*       out  = (float*)d_out;

    transpose_x<<<dim3(E_ / 64, B_), 256>>>(x);

    cudaFuncSetAttribute(meshconv_kernel,
                         cudaFuncAttributeMaxDynamicSharedMemorySize, SM_TOTAL);
    meshconv_kernel<<<NCTA, NTHR, SM_TOTAL>>>(Gi, W, bias, out);
}